// round 2
// baseline (speedup 1.0000x reference)
#include <cuda_runtime.h>
#include <cuda_bf16.h>

#define VOCAB 32000
#define EMBED 32
#define HID   16
#define SEQ   128
#define BATCH 32
#define G4    64      // 4*HID
#define NB3   63      // K3/K4 blocks per timestep (512 vocab each)
#define PER_T (2*NB3)

// ---------------- scratch (device globals; no allocation) ----------------
__device__ float g_XG[SEQ * G4 * BATCH];   // [t][j][b]
__device__ float g_H [SEQ * HID * BATCH];  // [t][k][b]
__device__ float g_rowsum[SEQ * BATCH];
__device__ unsigned g_flagH[SEQ];
__device__ unsigned g_cnt3[SEQ];

// ---------------- f32x2 helpers ----------------
__device__ __forceinline__ unsigned long long pk2(float lo, float hi) {
    unsigned long long r;
    asm("mov.b64 %0, {%1, %2};" : "=l"(r) : "f"(lo), "f"(hi));
    return r;
}
__device__ __forceinline__ unsigned long long fma2(unsigned long long a,
                                                   unsigned long long b,
                                                   unsigned long long c) {
    unsigned long long d;
    asm("fma.rn.f32x2 %0, %1, %2, %3;" : "=l"(d) : "l"(a), "l"(b), "l"(c));
    return d;
}
__device__ __forceinline__ float hsum2(unsigned long long v) {
    float lo, hi;
    asm("mov.b64 {%0, %1}, %2;" : "=f"(lo), "=f"(hi) : "l"(v));
    return lo + hi;
}
__device__ __forceinline__ float dot16x2(const unsigned long long* w,
                                         const unsigned long long* x) {
    unsigned long long acc = 0ull;
#pragma unroll
    for (int p = 0; p < 8; p++) acc = fma2(w[p], x[p], acc);
    return hsum2(acc);
}
__device__ __forceinline__ float fsigm(float x) {
    return __fdividef(1.f, 1.f + __expf(-x));
}
__device__ __forceinline__ float ftanh(float x) {
    float e = __expf(-2.f * x);
    return (1.f - e) * __fdividef(1.f, 1.f + e);
}
__device__ __forceinline__ unsigned ld_acq(const unsigned* p) {
    unsigned v;
    asm volatile("ld.acquire.gpu.u32 %0, [%1];" : "=r"(v) : "l"(p) : "memory");
    return v;
}

// ---------------- K1: input-side gates + scratch reset ----------------
__global__ __launch_bounds__(256) void k1_xgates(
    const int* __restrict__ idx, const float* __restrict__ emb,
    const float* __restrict__ Wih, const float* __restrict__ bih,
    const float* __restrict__ bhh) {
    __shared__ float xs[BATCH][EMBED + 1];
    __shared__ float ws[G4][EMBED];
    __shared__ float bias[G4];
    const int t = blockIdx.x, tid = threadIdx.x;

    if (tid == 0) { g_flagH[t] = 0u; g_cnt3[t] = 0u; }
    if (tid < BATCH) g_rowsum[t * BATCH + tid] = 0.f;

    for (int i = tid; i < BATCH * EMBED; i += 256) {
        int b = i >> 5, e = i & 31;
        xs[b][e] = emb[idx[t * BATCH + b] * EMBED + e];
    }
    for (int i = tid; i < G4 * EMBED; i += 256) ws[i >> 5][i & 31] = Wih[i];
    if (tid < G4) bias[tid] = bih[tid] + bhh[tid];
    __syncthreads();

    for (int i = tid; i < G4 * BATCH; i += 256) {
        int j = i >> 5, b = i & 31;
        float acc = bias[j];
#pragma unroll
        for (int e = 0; e < EMBED; e++) acc = fmaf(xs[b][e], ws[j][e], acc);
        g_XG[(t * G4 + j) * BATCH + b] = acc;
    }
}

// ---------------- fused: producer(LSTM) + K3(sumexp) + K4(write) ----------
__global__ __launch_bounds__(256, 4) void k_fused(
    const float* __restrict__ Whh, const float* __restrict__ h0,
    const float* __restrict__ c0,  const float* __restrict__ Wout,
    const float* __restrict__ bout, float* __restrict__ out) {
    const int tid = threadIdx.x;

    if (blockIdx.x == 0) {
        // ======== producer: 16 units x 16 lanes, 2 batches/thread ========
        const int u = tid >> 4, l = tid & 15;
        const int b0 = l, b1 = l + 16;
        __shared__ float hs[2][HID][BATCH];
        __shared__ unsigned long long wp[4][HID][8];

        for (int i = tid; i < 4 * HID * 8; i += 256) {
            int g = i >> 7, rest = i & 127, uu = rest >> 3, p = rest & 7;
            const float* row = Whh + (g * HID + uu) * HID;
            wp[g][uu][p] = pk2(row[2 * p], row[2 * p + 1]);
        }
        for (int i = tid; i < HID * BATCH; i += 256) {
            int uu = i >> 5, b = i & 31;
            hs[0][uu][b] = h0[b * HID + uu];
        }
        float cc0 = c0[b0 * HID + u], cc1 = c0[b1 * HID + u];

        float xgn0[4], xgn1[4];
#pragma unroll
        for (int g = 0; g < 4; g++) {
            xgn0[g] = g_XG[(g * HID + u) * BATCH + b0];
            xgn1[g] = g_XG[(g * HID + u) * BATCH + b1];
        }
        __syncthreads();

        int cur = 0;
        for (int t = 0; t < SEQ; t++) {
            float xg0[4], xg1[4];
#pragma unroll
            for (int g = 0; g < 4; g++) { xg0[g] = xgn0[g]; xg1[g] = xgn1[g]; }
            if (t + 1 < SEQ) {
                const float* base = g_XG + (t + 1) * G4 * BATCH;
#pragma unroll
                for (int g = 0; g < 4; g++) {
                    xgn0[g] = base[(g * HID + u) * BATCH + b0];
                    xgn1[g] = base[(g * HID + u) * BATCH + b1];
                }
            }
            unsigned long long h2a[8], h2b[8];
#pragma unroll
            for (int p = 0; p < 8; p++) {
                h2a[p] = pk2(hs[cur][2 * p][b0], hs[cur][2 * p + 1][b0]);
                h2b[p] = pk2(hs[cur][2 * p][b1], hs[cur][2 * p + 1][b1]);
            }
            float ga[4], gb[4];
#pragma unroll
            for (int g = 0; g < 4; g++) {
                unsigned long long a0 = 0ull, a1 = 0ull;
#pragma unroll
                for (int p = 0; p < 8; p++) {
                    unsigned long long w = wp[g][u][p];
                    a0 = fma2(w, h2a[p], a0);
                    a1 = fma2(w, h2b[p], a1);
                }
                ga[g] = hsum2(a0) + xg0[g];
                gb[g] = hsum2(a1) + xg1[g];
            }
            float hn0, hn1;
            {
                float ii = fsigm(ga[0]), ff = fsigm(ga[1]);
                float gg = ftanh(ga[2]), oo = fsigm(ga[3]);
                cc0 = ff * cc0 + ii * gg;
                hn0 = oo * ftanh(cc0);
            }
            {
                float ii = fsigm(gb[0]), ff = fsigm(gb[1]);
                float gg = ftanh(gb[2]), oo = fsigm(gb[3]);
                cc1 = ff * cc1 + ii * gg;
                hn1 = oo * ftanh(cc1);
            }
            hs[cur ^ 1][u][b0] = hn0;
            hs[cur ^ 1][u][b1] = hn1;
            float* gh = g_H + t * (HID * BATCH);
            gh[u * BATCH + b0] = hn0;
            gh[u * BATCH + b1] = hn1;
            __syncthreads();
            if (tid == 0) { __threadfence(); atomicExch(&g_flagH[t], 1u); }
            cur ^= 1;
        }
        return;
    }

    // ======== consumers ========
    const int r = blockIdx.x - 1;
    const int t = r / PER_T;
    const int q = r % PER_T;

    __shared__ unsigned long long h2s[BATCH][8];

    if (q < NB3) {
        // ---------- K3: sum(exp(logits)) ----------
        const int chunk = q;
        __shared__ float bsum[BATCH];
        if (tid == 0) {
            while (ld_acq(&g_flagH[t]) == 0u) __nanosleep(64);
        }
        __syncthreads();
        if (tid < BATCH) bsum[tid] = 0.f;
        {
            int b = tid >> 3, p = tid & 7;
            h2s[b][p] = pk2(g_H[t * (HID * BATCH) + (2 * p) * BATCH + b],
                            g_H[t * (HID * BATCH) + (2 * p + 1) * BATCH + b]);
        }
        __syncthreads();

        const int v0 = chunk * 512 + tid;
        const int v1 = v0 + 256;
        const bool ok0 = v0 < VOCAB, ok1 = v1 < VOCAB;

        unsigned long long w0[8], w1[8];
        float bb0 = 0.f, bb1 = 0.f;
        if (ok0) {
            const float4* wv = (const float4*)(Wout + v0 * HID);
#pragma unroll
            for (int qq = 0; qq < 4; qq++) {
                float4 f = wv[qq];
                w0[2 * qq] = pk2(f.x, f.y); w0[2 * qq + 1] = pk2(f.z, f.w);
            }
            bb0 = bout[v0];
        } else {
#pragma unroll
            for (int p = 0; p < 8; p++) w0[p] = 0ull;
        }
        if (ok1) {
            const float4* wv = (const float4*)(Wout + v1 * HID);
#pragma unroll
            for (int qq = 0; qq < 4; qq++) {
                float4 f = wv[qq];
                w1[2 * qq] = pk2(f.x, f.y); w1[2 * qq + 1] = pk2(f.z, f.w);
            }
            bb1 = bout[v1];
        } else {
#pragma unroll
            for (int p = 0; p < 8; p++) w1[p] = 0ull;
        }

        const int lane = tid & 31;
#pragma unroll 4
        for (int b = 0; b < BATCH; b++) {
            unsigned long long h2[8];
#pragma unroll
            for (int p = 0; p < 8; p++) h2[p] = h2s[b][p];
            float l0 = dot16x2(w0, h2) + bb0;
            float l1 = dot16x2(w1, h2) + bb1;
            float e = (ok0 ? __expf(l0) : 0.f) + (ok1 ? __expf(l1) : 0.f);
#pragma unroll
            for (int m = 16; m > 0; m >>= 1) e += __shfl_xor_sync(0xffffffffu, e, m);
            if (lane == 0) atomicAdd(&bsum[b], e);
        }
        __syncthreads();
        if (tid < BATCH) atomicAdd(&g_rowsum[t * BATCH + tid], bsum[tid]);
        __syncthreads();
        if (tid == 0) { __threadfence(); atomicAdd(&g_cnt3[t], 1u); }
    } else {
        // ---------- K4: write logprobs ----------
        const int chunk = q - NB3;
        __shared__ float lse[BATCH];
        if (tid == 0) {
            while (ld_acq(&g_cnt3[t]) < (unsigned)NB3) __nanosleep(128);
        }
        __syncthreads();
        if (tid < BATCH) lse[tid] = __logf(g_rowsum[t * BATCH + tid]);
        {
            int b = tid >> 3, p = tid & 7;
            h2s[b][p] = pk2(g_H[t * (HID * BATCH) + (2 * p) * BATCH + b],
                            g_H[t * (HID * BATCH) + (2 * p + 1) * BATCH + b]);
        }
        __syncthreads();

        const int v0 = chunk * 512 + tid;
        const int v1 = v0 + 256;
        const bool ok0 = v0 < VOCAB, ok1 = v1 < VOCAB;

        unsigned long long w0[8], w1[8];
        float bb0 = 0.f, bb1 = 0.f;
        if (ok0) {
            const float4* wv = (const float4*)(Wout + v0 * HID);
#pragma unroll
            for (int qq = 0; qq < 4; qq++) {
                float4 f = wv[qq];
                w0[2 * qq] = pk2(f.x, f.y); w0[2 * qq + 1] = pk2(f.z, f.w);
            }
            bb0 = bout[v0];
        } else {
#pragma unroll
            for (int p = 0; p < 8; p++) w0[p] = 0ull;
        }
        if (ok1) {
            const float4* wv = (const float4*)(Wout + v1 * HID);
#pragma unroll
            for (int qq = 0; qq < 4; qq++) {
                float4 f = wv[qq];
                w1[2 * qq] = pk2(f.x, f.y); w1[2 * qq + 1] = pk2(f.z, f.w);
            }
            bb1 = bout[v1];
        } else {
#pragma unroll
            for (int p = 0; p < 8; p++) w1[p] = 0ull;
        }

        float* orow = out + (size_t)t * BATCH * VOCAB;
#pragma unroll 4
        for (int b = 0; b < BATCH; b++) {
            unsigned long long h2[8];
#pragma unroll
            for (int p = 0; p < 8; p++) h2[p] = h2s[b][p];
            float L = lse[b];
            float l0 = dot16x2(w0, h2) + bb0;
            float l1 = dot16x2(w1, h2) + bb1;
            if (ok0) orow[(size_t)b * VOCAB + v0] = l0 - L;
            if (ok1) orow[(size_t)b * VOCAB + v1] = l1 - L;
        }
    }
}

// ---------------- launch ----------------
extern "C" void kernel_launch(void* const* d_in, const int* in_sizes, int n_in,
                              void* d_out, int out_size) {
    const int*   idx  = (const int*)  d_in[0];
    const float* emb  = (const float*)d_in[1];
    const float* Wih  = (const float*)d_in[2];
    const float* Whh  = (const float*)d_in[3];
    const float* bih  = (const float*)d_in[4];
    const float* bhh  = (const float*)d_in[5];
    const float* Wout = (const float*)d_in[6];
    const float* bout = (const float*)d_in[7];
    const float* h0   = (const float*)d_in[8];
    const float* c0   = (const float*)d_in[9];
    float* out = (float*)d_out;

    k1_xgates<<<SEQ, 256>>>(idx, emb, Wih, bih, bhh);
    k_fused<<<1 + SEQ * PER_T, 256>>>(Whh, h0, c0, Wout, bout, out);
}

// round 3
// speedup vs baseline: 1.0803x; 1.0803x over previous
#include <cuda_runtime.h>
#include <cuda_bf16.h>

#define VOCAB 32000
#define EMBED 32
#define HID   16
#define SEQ   128
#define BATCH 32
#define G4    64
#define NCHUNK 63      // 512-vocab chunks (63*512 = 32256 >= 32000)
#define NGROUP 4       // t strided by 4 across groups

// ---------------- scratch (device globals; no allocation) ----------------
__device__ float g_XG[SEQ * G4 * BATCH];   // [t][gate*HID+u][b]
__device__ float g_H [SEQ * HID * BATCH];  // [t][k][b]
__device__ float g_rowsum[SEQ * BATCH];
__device__ unsigned g_flagH[SEQ];
__device__ unsigned g_cnt3[SEQ];

// ---------------- helpers ----------------
__device__ __forceinline__ unsigned long long pk2(float lo, float hi) {
    unsigned long long r;
    asm("mov.b64 %0, {%1, %2};" : "=l"(r) : "f"(lo), "f"(hi));
    return r;
}
__device__ __forceinline__ unsigned long long fma2(unsigned long long a,
                                                   unsigned long long b,
                                                   unsigned long long c) {
    unsigned long long d;
    asm("fma.rn.f32x2 %0, %1, %2, %3;" : "=l"(d) : "l"(a), "l"(b), "l"(c));
    return d;
}
__device__ __forceinline__ float hsum2(unsigned long long v) {
    float lo, hi;
    asm("mov.b64 {%0, %1}, %2;" : "=f"(lo), "=f"(hi) : "l"(v));
    return lo + hi;
}
__device__ __forceinline__ float tanha(float x) {
    float y;
    asm("tanh.approx.f32 %0, %1;" : "=f"(y) : "f"(x));
    return y;
}
__device__ __forceinline__ float sgm(float x) {        // sigmoid via tanh
    return fmaf(tanha(0.5f * x), 0.5f, 0.5f);
}
__device__ __forceinline__ unsigned ld_acq(const unsigned* p) {
    unsigned v;
    asm volatile("ld.acquire.gpu.u32 %0, [%1];" : "=r"(v) : "l"(p) : "memory");
    return v;
}
__device__ __forceinline__ float ld_acq_f(const float* p) {
    float v;
    asm volatile("ld.acquire.gpu.f32 %0, [%1];" : "=f"(v) : "l"(p) : "memory");
    return v;
}

// ---------------- K1: input-side gate preacts + scratch reset ----------------
__global__ __launch_bounds__(256) void k1_xgates(
    const int* __restrict__ idx, const float* __restrict__ emb,
    const float* __restrict__ Wih, const float* __restrict__ bih,
    const float* __restrict__ bhh) {
    __shared__ float xs[BATCH][EMBED + 1];
    __shared__ float ws[G4][EMBED];
    __shared__ float bias[G4];
    const int t = blockIdx.x, tid = threadIdx.x;

    if (tid == 0) { g_flagH[t] = 0u; g_cnt3[t] = 0u; }
    if (tid < BATCH) g_rowsum[t * BATCH + tid] = 0.f;

    for (int i = tid; i < BATCH * EMBED; i += 256) {
        int b = i >> 5, e = i & 31;
        xs[b][e] = emb[idx[t * BATCH + b] * EMBED + e];
    }
    for (int i = tid; i < G4 * EMBED; i += 256) ws[i >> 5][i & 31] = Wih[i];
    if (tid < G4) bias[tid] = bih[tid] + bhh[tid];
    __syncthreads();

    for (int i = tid; i < G4 * BATCH; i += 256) {
        int j = i >> 5, b = i & 31;
        float acc = bias[j];
#pragma unroll
        for (int e = 0; e < EMBED; e++) acc = fmaf(xs[b][e], ws[j][e], acc);
        g_XG[(t * G4 + j) * BATCH + b] = acc;
    }
}

// ---------------- persistent mono-kernel: producer + single-pass GEMM ------
__global__ __launch_bounds__(256, 2) void k_mono(
    const float* __restrict__ Whh, const float* __restrict__ h0,
    const float* __restrict__ c0,  const float* __restrict__ Wout,
    const float* __restrict__ bout, float* __restrict__ out) {
    const int tid = threadIdx.x;

    if (blockIdx.x == 0) {
        // ================= producer: LSTM recurrence =================
        const int u = tid >> 4, l = tid & 15;
        const int b0 = l, b1 = l + 16;
        __shared__ float hs[2][HID][BATCH];
        __shared__ unsigned long long wp[4][HID][8];

        for (int i = tid; i < 4 * HID * 8; i += 256) {
            int g = i >> 7, rest = i & 127, uu = rest >> 3, p = rest & 7;
            const float* row = Whh + (g * HID + uu) * HID;
            wp[g][uu][p] = pk2(row[2 * p], row[2 * p + 1]);
        }
        for (int i = tid; i < HID * BATCH; i += 256) {
            int uu = i >> 5, b = i & 31;
            hs[0][uu][b] = h0[b * HID + uu];
        }
        float cc0 = c0[b0 * HID + u], cc1 = c0[b1 * HID + u];

        float xgn0[4], xgn1[4];
#pragma unroll
        for (int g = 0; g < 4; g++) {
            xgn0[g] = g_XG[(g * HID + u) * BATCH + b0];
            xgn1[g] = g_XG[(g * HID + u) * BATCH + b1];
        }
        __syncthreads();

        int cur = 0;
        for (int t = 0; t < SEQ; t++) {
            float xg0[4], xg1[4];
#pragma unroll
            for (int g = 0; g < 4; g++) { xg0[g] = xgn0[g]; xg1[g] = xgn1[g]; }
            if (t + 1 < SEQ) {
                const float* base = g_XG + (t + 1) * G4 * BATCH;
#pragma unroll
                for (int g = 0; g < 4; g++) {
                    xgn0[g] = base[(g * HID + u) * BATCH + b0];
                    xgn1[g] = base[(g * HID + u) * BATCH + b1];
                }
            }
            unsigned long long h2a[8], h2b[8];
#pragma unroll
            for (int p = 0; p < 8; p++) {
                h2a[p] = pk2(hs[cur][2 * p][b0], hs[cur][2 * p + 1][b0]);
                h2b[p] = pk2(hs[cur][2 * p][b1], hs[cur][2 * p + 1][b1]);
            }
            float ga[4], gb[4];
#pragma unroll
            for (int g = 0; g < 4; g++) {
                unsigned long long a0 = 0ull, a1 = 0ull;
#pragma unroll
                for (int p = 0; p < 8; p++) {
                    unsigned long long w = wp[g][u][p];
                    a0 = fma2(w, h2a[p], a0);
                    a1 = fma2(w, h2b[p], a1);
                }
                ga[g] = hsum2(a0) + xg0[g];
                gb[g] = hsum2(a1) + xg1[g];
            }
            float hn0, hn1;
            {
                float ii = sgm(ga[0]), ff = sgm(ga[1]);
                float gg = tanha(ga[2]), oo = sgm(ga[3]);
                cc0 = ff * cc0 + ii * gg;
                hn0 = oo * tanha(cc0);
            }
            {
                float ii = sgm(gb[0]), ff = sgm(gb[1]);
                float gg = tanha(gb[2]), oo = sgm(gb[3]);
                cc1 = ff * cc1 + ii * gg;
                hn1 = oo * tanha(cc1);
            }
            hs[cur ^ 1][u][b0] = hn0;
            hs[cur ^ 1][u][b1] = hn1;
            float* gh = g_H + t * (HID * BATCH);
            gh[u * BATCH + b0] = hn0;
            gh[u * BATCH + b1] = hn1;
            __syncthreads();
            if (tid == 0) { __threadfence(); atomicExch(&g_flagH[t], 1u); }
            cur ^= 1;
        }
        return;
    }

    // ================= consumers: single-pass logits + logsumexp =========
    const int bid   = blockIdx.x - 1;
    const int chunk = bid % NCHUNK;
    const int g     = bid / NCHUNK;          // 0..3
    const int v0    = chunk * 512 + 2 * tid; // this thread: vocab v0, v0+1
    const bool ok   = v0 < VOCAB;            // VOCAB even -> covers v0+1 too

    // weights for 2 vocab rows, resident in registers for ALL timesteps
    unsigned long long w0[8], w1[8];
    float bb0 = 0.f, bb1 = 0.f;
    if (ok) {
        const float4* wv = (const float4*)(Wout + (size_t)v0 * HID);
#pragma unroll
        for (int q = 0; q < 4; q++) {
            float4 f = wv[q];
            w0[2 * q] = pk2(f.x, f.y); w0[2 * q + 1] = pk2(f.z, f.w);
        }
#pragma unroll
        for (int q = 0; q < 4; q++) {
            float4 f = wv[4 + q];
            w1[2 * q] = pk2(f.x, f.y); w1[2 * q + 1] = pk2(f.z, f.w);
        }
        bb0 = bout[v0]; bb1 = bout[v0 + 1];
    } else {
#pragma unroll
        for (int p = 0; p < 8; p++) { w0[p] = 0ull; w1[p] = 0ull; }
    }

    __shared__ __align__(16) unsigned long long h2s[BATCH][8];
    __shared__ float bsum[BATCH];
    __shared__ float lseS[BATCH];
    float l0[BATCH], l1[BATCH];

    for (int t = g; t < SEQ; t += NGROUP) {
        if (tid == 0) {
            while (ld_acq(&g_flagH[t]) == 0u) __nanosleep(32);
        }
        __syncthreads();
        {   // stage h(t) as k-packed f32x2
            int b = tid >> 3, p = tid & 7;
            const float* gh = g_H + t * (HID * BATCH);
            h2s[b][p] = pk2(__ldcg(gh + (2 * p) * BATCH + b),
                            __ldcg(gh + (2 * p + 1) * BATCH + b));
        }
        if (tid < BATCH) bsum[tid] = 0.f;
        __syncthreads();

#pragma unroll
        for (int b = 0; b < BATCH; b++) {
            unsigned long long a0 = pk2(bb0, 0.f);
            unsigned long long a1 = pk2(bb1, 0.f);
#pragma unroll
            for (int p = 0; p < 8; p++) {
                unsigned long long h = h2s[b][p];
                a0 = fma2(w0[p], h, a0);
                a1 = fma2(w1[p], h, a1);
            }
            l0[b] = hsum2(a0);
            l1[b] = hsum2(a1);
            float e = ok ? (__expf(l0[b]) + __expf(l1[b])) : 0.f;
#pragma unroll
            for (int m = 16; m > 0; m >>= 1)
                e += __shfl_xor_sync(0xffffffffu, e, m);
            if ((tid & 31) == 0) atomicAdd(&bsum[b], e);
        }
        __syncthreads();
        if (tid < BATCH) atomicAdd(&g_rowsum[t * BATCH + tid], bsum[tid]);
        __threadfence();
        __syncthreads();
        if (tid == 0) {
            atomicAdd(&g_cnt3[t], 1u);
            while (ld_acq(&g_cnt3[t]) < (unsigned)NCHUNK) __nanosleep(32);
        }
        __syncthreads();
        if (tid < BATCH) lseS[tid] = __logf(ld_acq_f(&g_rowsum[t * BATCH + tid]));
        __syncthreads();

        if (ok) {
            float* orow = out + ((size_t)t * BATCH) * VOCAB + v0;
#pragma unroll
            for (int b = 0; b < BATCH; b++) {
                float L = lseS[b];
                float2 o = make_float2(l0[b] - L, l1[b] - L);
                *(float2*)(orow + (size_t)b * VOCAB) = o;
            }
        }
    }
}

// ---------------- launch ----------------
extern "C" void kernel_launch(void* const* d_in, const int* in_sizes, int n_in,
                              void* d_out, int out_size) {
    const int*   idx  = (const int*)  d_in[0];
    const float* emb  = (const float*)d_in[1];
    const float* Wih  = (const float*)d_in[2];
    const float* Whh  = (const float*)d_in[3];
    const float* bih  = (const float*)d_in[4];
    const float* bhh  = (const float*)d_in[5];
    const float* Wout = (const float*)d_in[6];
    const float* bout = (const float*)d_in[7];
    const float* h0   = (const float*)d_in[8];
    const float* c0   = (const float*)d_in[9];
    float* out = (float*)d_out;

    k1_xgates<<<SEQ, 256>>>(idx, emb, Wih, bih, bhh);
    k_mono<<<1 + NCHUNK * NGROUP, 256>>>(Whh, h0, c0, Wout, bout, out);
}

// round 4
// speedup vs baseline: 1.2067x; 1.1170x over previous
#include <cuda_runtime.h>
#include <cuda_bf16.h>

#define VOCAB 32000
#define EMBED 32
#define HID   16
#define SEQ   128
#define BATCH 32
#define G4    64
#define NCHUNK 63      // 512-vocab chunks per timestep (63*512 >= 32000)

// ---------------- scratch (device globals; no allocation) ----------------
__device__ float g_XG[SEQ * G4 * BATCH];   // [t][gate*HID+u][b]
__device__ float g_H [SEQ * HID * BATCH];  // [t][k][b]
__device__ float g_rowsum[SEQ * BATCH];
__device__ unsigned g_flagH[SEQ];

// ---------------- helpers ----------------
__device__ __forceinline__ unsigned long long pk2(float lo, float hi) {
    unsigned long long r;
    asm("mov.b64 %0, {%1, %2};" : "=l"(r) : "f"(lo), "f"(hi));
    return r;
}
__device__ __forceinline__ unsigned long long fma2(unsigned long long a,
                                                   unsigned long long b,
                                                   unsigned long long c) {
    unsigned long long d;
    asm("fma.rn.f32x2 %0, %1, %2, %3;" : "=l"(d) : "l"(a), "l"(b), "l"(c));
    return d;
}
__device__ __forceinline__ float hsum2(unsigned long long v) {
    float lo, hi;
    asm("mov.b64 {%0, %1}, %2;" : "=f"(lo), "=f"(hi) : "l"(v));
    return lo + hi;
}
__device__ __forceinline__ float tanha(float x) {
    float y;
    asm("tanh.approx.f32 %0, %1;" : "=f"(y) : "f"(x));
    return y;
}
__device__ __forceinline__ float sgm(float x) {
    return fmaf(tanha(0.5f * x), 0.5f, 0.5f);
}
__device__ __forceinline__ unsigned ld_acq(const unsigned* p) {
    unsigned v;
    asm volatile("ld.acquire.gpu.u32 %0, [%1];" : "=r"(v) : "l"(p) : "memory");
    return v;
}
__device__ __forceinline__ void stcs2(float* p, float2 v) {
    asm volatile("st.global.cs.v2.f32 [%0], {%1, %2};" :: "l"(p), "f"(v.x), "f"(v.y) : "memory");
}

// ---------------- K1: input-side gate preacts + scratch reset --------------
__global__ __launch_bounds__(256) void k1_xgates(
    const int* __restrict__ idx, const float* __restrict__ emb,
    const float* __restrict__ Wih, const float* __restrict__ bih,
    const float* __restrict__ bhh) {
    __shared__ float xs[BATCH][EMBED + 1];
    __shared__ float ws[G4][EMBED];
    __shared__ float bias[G4];
    const int t = blockIdx.x, tid = threadIdx.x;

    if (tid == 0) g_flagH[t] = 0u;
    if (tid < BATCH) g_rowsum[t * BATCH + tid] = 0.f;

    for (int i = tid; i < BATCH * EMBED; i += 256) {
        int b = i >> 5, e = i & 31;
        xs[b][e] = emb[idx[t * BATCH + b] * EMBED + e];
    }
    for (int i = tid; i < G4 * EMBED; i += 256) ws[i >> 5][i & 31] = Wih[i];
    if (tid < G4) bias[tid] = bih[tid] + bhh[tid];
    __syncthreads();

    for (int i = tid; i < G4 * BATCH; i += 256) {
        int j = i >> 5, b = i & 31;
        float acc = bias[j];
#pragma unroll
        for (int e = 0; e < EMBED; e++) acc = fmaf(xs[b][e], ws[j][e], acc);
        g_XG[(t * G4 + j) * BATCH + b] = acc;
    }
}

// ---------------- K23: producer (block 0) + sumexp consumers ---------------
__global__ __launch_bounds__(256, 4) void k23_fused(
    const float* __restrict__ Whh, const float* __restrict__ h0,
    const float* __restrict__ c0,  const float* __restrict__ Wout,
    const float* __restrict__ bout) {
    const int tid = threadIdx.x;

    if (blockIdx.x == 0) {
        // ============ producer: LSTM recurrence ============
        const int u = tid >> 4, l = tid & 15;
        const int b0 = l, b1 = l + 16;
        __shared__ float hs[2][HID][BATCH];
        __shared__ unsigned long long wp[4][HID][8];

        for (int i = tid; i < 4 * HID * 8; i += 256) {
            int g = i >> 7, rest = i & 127, uu = rest >> 3, p = rest & 7;
            const float* row = Whh + (g * HID + uu) * HID;
            wp[g][uu][p] = pk2(row[2 * p], row[2 * p + 1]);
        }
        for (int i = tid; i < HID * BATCH; i += 256) {
            int uu = i >> 5, b = i & 31;
            hs[0][uu][b] = h0[b * HID + uu];
        }
        float cc0 = c0[b0 * HID + u], cc1 = c0[b1 * HID + u];

        float xgn0[4], xgn1[4];
#pragma unroll
        for (int g = 0; g < 4; g++) {
            xgn0[g] = g_XG[(g * HID + u) * BATCH + b0];
            xgn1[g] = g_XG[(g * HID + u) * BATCH + b1];
        }
        __syncthreads();

        int cur = 0;
        for (int t = 0; t < SEQ; t++) {
            float xg0[4], xg1[4];
#pragma unroll
            for (int g = 0; g < 4; g++) { xg0[g] = xgn0[g]; xg1[g] = xgn1[g]; }
            if (t + 1 < SEQ) {
                const float* base = g_XG + (t + 1) * G4 * BATCH;
#pragma unroll
                for (int g = 0; g < 4; g++) {
                    xgn0[g] = base[(g * HID + u) * BATCH + b0];
                    xgn1[g] = base[(g * HID + u) * BATCH + b1];
                }
            }
            unsigned long long h2a[8], h2b[8];
#pragma unroll
            for (int p = 0; p < 8; p++) {
                h2a[p] = pk2(hs[cur][2 * p][b0], hs[cur][2 * p + 1][b0]);
                h2b[p] = pk2(hs[cur][2 * p][b1], hs[cur][2 * p + 1][b1]);
            }
            float ga[4], gb[4];
#pragma unroll
            for (int g = 0; g < 4; g++) {
                unsigned long long a0 = 0ull, a1 = 0ull;
#pragma unroll
                for (int p = 0; p < 8; p++) {
                    unsigned long long w = wp[g][u][p];
                    a0 = fma2(w, h2a[p], a0);
                    a1 = fma2(w, h2b[p], a1);
                }
                ga[g] = hsum2(a0) + xg0[g];
                gb[g] = hsum2(a1) + xg1[g];
            }
            float hn0, hn1;
            {
                float ii = sgm(ga[0]), ff = sgm(ga[1]);
                float gg = tanha(ga[2]), oo = sgm(ga[3]);
                cc0 = ff * cc0 + ii * gg;
                hn0 = oo * tanha(cc0);
            }
            {
                float ii = sgm(gb[0]), ff = sgm(gb[1]);
                float gg = tanha(gb[2]), oo = sgm(gb[3]);
                cc1 = ff * cc1 + ii * gg;
                hn1 = oo * tanha(cc1);
            }
            hs[cur ^ 1][u][b0] = hn0;
            hs[cur ^ 1][u][b1] = hn1;
            float* gh = g_H + t * (HID * BATCH);
            gh[u * BATCH + b0] = hn0;
            gh[u * BATCH + b1] = hn1;
            __syncthreads();
            if (tid == 0) { __threadfence(); atomicExch(&g_flagH[t], 1u); }
            cur ^= 1;
        }
        return;
    }

    // ============ consumers: sum(exp(logits)) for one (t, chunk) ============
    const int bid   = blockIdx.x - 1;
    const int t     = bid / NCHUNK;        // ascending with block index
    const int chunk = bid % NCHUNK;
    const int v0    = chunk * 512 + 2 * tid;
    const bool ok   = v0 < VOCAB;

    unsigned long long w0[8], w1[8];
    float bb0 = 0.f, bb1 = 0.f;
    if (ok) {
        const float4* wv = (const float4*)(Wout + (size_t)v0 * HID);
#pragma unroll
        for (int q = 0; q < 4; q++) {
            float4 f = wv[q];
            w0[2 * q] = pk2(f.x, f.y); w0[2 * q + 1] = pk2(f.z, f.w);
        }
#pragma unroll
        for (int q = 0; q < 4; q++) {
            float4 f = wv[4 + q];
            w1[2 * q] = pk2(f.x, f.y); w1[2 * q + 1] = pk2(f.z, f.w);
        }
        bb0 = bout[v0]; bb1 = bout[v0 + 1];
    } else {
#pragma unroll
        for (int p = 0; p < 8; p++) { w0[p] = 0ull; w1[p] = 0ull; }
    }

    __shared__ __align__(16) unsigned long long h2s[BATCH][8];
    __shared__ float bsum[BATCH];

    if (tid == 0) {
        while (ld_acq(&g_flagH[t]) == 0u) __nanosleep(32);
    }
    __syncthreads();
    {
        int b = tid >> 3, p = tid & 7;
        const float* gh = g_H + t * (HID * BATCH);
        h2s[b][p] = pk2(__ldcg(gh + (2 * p) * BATCH + b),
                        __ldcg(gh + (2 * p + 1) * BATCH + b));
    }
    if (tid < BATCH) bsum[tid] = 0.f;
    __syncthreads();

    const int lane = tid & 31;
#pragma unroll 4
    for (int b = 0; b < BATCH; b++) {
        unsigned long long a0 = pk2(bb0, 0.f);
        unsigned long long a1 = pk2(bb1, 0.f);
#pragma unroll
        for (int p = 0; p < 8; p++) {
            unsigned long long h = h2s[b][p];
            a0 = fma2(w0[p], h, a0);
            a1 = fma2(w1[p], h, a1);
        }
        float e = ok ? (__expf(hsum2(a0)) + __expf(hsum2(a1))) : 0.f;
#pragma unroll
        for (int m = 16; m > 0; m >>= 1)
            e += __shfl_xor_sync(0xffffffffu, e, m);
        if (lane == 0) atomicAdd(&bsum[b], e);
    }
    __syncthreads();
    if (tid < BATCH) atomicAdd(&g_rowsum[t * BATCH + tid], bsum[tid]);
}

// ---------------- K4: write logprobs (no dependencies, no spins) -----------
__global__ __launch_bounds__(256, 4) void k4_write(
    const float* __restrict__ Wout, const float* __restrict__ bout,
    float* __restrict__ out) {
    const int t = blockIdx.y, tid = threadIdx.x;
    const int chunk = blockIdx.x;
    const int v0 = chunk * 512 + 2 * tid;
    const bool ok = v0 < VOCAB;

    unsigned long long w0[8], w1[8];
    float bb0 = 0.f, bb1 = 0.f;
    if (ok) {
        const float4* wv = (const float4*)(Wout + (size_t)v0 * HID);
#pragma unroll
        for (int q = 0; q < 4; q++) {
            float4 f = wv[q];
            w0[2 * q] = pk2(f.x, f.y); w0[2 * q + 1] = pk2(f.z, f.w);
        }
#pragma unroll
        for (int q = 0; q < 4; q++) {
            float4 f = wv[4 + q];
            w1[2 * q] = pk2(f.x, f.y); w1[2 * q + 1] = pk2(f.z, f.w);
        }
        bb0 = bout[v0]; bb1 = bout[v0 + 1];
    } else {
#pragma unroll
        for (int p = 0; p < 8; p++) { w0[p] = 0ull; w1[p] = 0ull; }
    }

    __shared__ __align__(16) unsigned long long h2s[BATCH][8];
    __shared__ float lseS[BATCH];
    if (tid < BATCH) lseS[tid] = __logf(g_rowsum[t * BATCH + tid]);
    {
        int b = tid >> 3, p = tid & 7;
        const float* gh = g_H + t * (HID * BATCH);
        h2s[b][p] = pk2(gh[(2 * p) * BATCH + b], gh[(2 * p + 1) * BATCH + b]);
    }
    __syncthreads();

    if (!ok) return;
    float* orow = out + ((size_t)t * BATCH) * VOCAB + v0;
#pragma unroll 4
    for (int b = 0; b < BATCH; b++) {
        unsigned long long a0 = pk2(bb0, 0.f);
        unsigned long long a1 = pk2(bb1, 0.f);
#pragma unroll
        for (int p = 0; p < 8; p++) {
            unsigned long long h = h2s[b][p];
            a0 = fma2(w0[p], h, a0);
            a1 = fma2(w1[p], h, a1);
        }
        float L = lseS[b];
        stcs2(orow + (size_t)b * VOCAB,
              make_float2(hsum2(a0) - L, hsum2(a1) - L));
    }
}

// ---------------- launch ----------------
extern "C" void kernel_launch(void* const* d_in, const int* in_sizes, int n_in,
                              void* d_out, int out_size) {
    const int*   idx  = (const int*)  d_in[0];
    const float* emb  = (const float*)d_in[1];
    const float* Wih  = (const float*)d_in[2];
    const float* Whh  = (const float*)d_in[3];
    const float* bih  = (const float*)d_in[4];
    const float* bhh  = (const float*)d_in[5];
    const float* Wout = (const float*)d_in[6];
    const float* bout = (const float*)d_in[7];
    const float* h0   = (const float*)d_in[8];
    const float* c0   = (const float*)d_in[9];
    float* out = (float*)d_out;

    k1_xgates<<<SEQ, 256>>>(idx, emb, Wih, bih, bhh);
    k23_fused<<<1 + SEQ * NCHUNK, 256>>>(Whh, h0, c0, Wout, bout);
    k4_write<<<dim3(NCHUNK, SEQ), 256>>>(Wout, bout, out);
}

// round 5
// speedup vs baseline: 1.3280x; 1.1005x over previous
#include <cuda_runtime.h>
#include <cuda_bf16.h>

#define VOCAB 32000
#define EMBED 32
#define HID   16
#define SEQ   128
#define BATCH 32
#define G4    64
#define NCHUNK 32      // 1024-vocab chunks per timestep (32*1024 >= 32000)

// ---------------- scratch (device globals; no allocation) ----------------
__device__ float g_XG[SEQ * G4 * BATCH];   // [t][gate*HID+u][b]
__device__ float g_H [SEQ * HID * BATCH];  // [t][k][b]
__device__ float g_rowsum[SEQ * BATCH];
__device__ unsigned g_flagH[SEQ];

// ---------------- helpers ----------------
__device__ __forceinline__ unsigned long long pk2(float lo, float hi) {
    unsigned long long r;
    asm("mov.b64 %0, {%1, %2};" : "=l"(r) : "f"(lo), "f"(hi));
    return r;
}
__device__ __forceinline__ unsigned long long fma2(unsigned long long a,
                                                   unsigned long long b,
                                                   unsigned long long c) {
    unsigned long long d;
    asm("fma.rn.f32x2 %0, %1, %2, %3;" : "=l"(d) : "l"(a), "l"(b), "l"(c));
    return d;
}
__device__ __forceinline__ float hsum2(unsigned long long v) {
    float lo, hi;
    asm("mov.b64 {%0, %1}, %2;" : "=f"(lo), "=f"(hi) : "l"(v));
    return lo + hi;
}
__device__ __forceinline__ float tanha(float x) {
    float y;
    asm("tanh.approx.f32 %0, %1;" : "=f"(y) : "f"(x));
    return y;
}
__device__ __forceinline__ float sgm(float x) {
    return fmaf(tanha(0.5f * x), 0.5f, 0.5f);
}
__device__ __forceinline__ unsigned ld_acq(const unsigned* p) {
    unsigned v;
    asm volatile("ld.acquire.gpu.u32 %0, [%1];" : "=r"(v) : "l"(p) : "memory");
    return v;
}

// load 4 weight rows (v0..v0+3) packed as f32x2, plus biases
__device__ __forceinline__ void load_w4(const float* __restrict__ Wout,
                                        const float* __restrict__ bout,
                                        int v0, bool ok,
                                        unsigned long long w[4][8], float bb[4]) {
    if (ok) {
        const float4* wv = (const float4*)(Wout + (size_t)v0 * HID);
#pragma unroll
        for (int r = 0; r < 4; r++) {
#pragma unroll
            for (int q = 0; q < 4; q++) {
                float4 f = wv[r * 4 + q];
                w[r][2 * q] = pk2(f.x, f.y);
                w[r][2 * q + 1] = pk2(f.z, f.w);
            }
            bb[r] = bout[v0 + r];
        }
    } else {
#pragma unroll
        for (int r = 0; r < 4; r++) {
#pragma unroll
            for (int p = 0; p < 8; p++) w[r][p] = 0ull;
            bb[r] = 0.f;
        }
    }
}

// ---------------- K1: input-side gate preacts + scratch reset --------------
__global__ __launch_bounds__(256) void k1_xgates(
    const int* __restrict__ idx, const float* __restrict__ emb,
    const float* __restrict__ Wih, const float* __restrict__ bih,
    const float* __restrict__ bhh) {
    __shared__ float xs[BATCH][EMBED + 1];
    __shared__ float ws[G4][EMBED];
    __shared__ float bias[G4];
    const int t = blockIdx.x, tid = threadIdx.x;

    if (tid == 0) g_flagH[t] = 0u;
    if (tid < BATCH) g_rowsum[t * BATCH + tid] = 0.f;

    for (int i = tid; i < BATCH * EMBED; i += 256) {
        int b = i >> 5, e = i & 31;
        xs[b][e] = emb[idx[t * BATCH + b] * EMBED + e];
    }
    for (int i = tid; i < G4 * EMBED; i += 256) ws[i >> 5][i & 31] = Wih[i];
    if (tid < G4) bias[tid] = bih[tid] + bhh[tid];
    __syncthreads();

    for (int i = tid; i < G4 * BATCH; i += 256) {
        int j = i >> 5, b = i & 31;
        float acc = bias[j];
#pragma unroll
        for (int e = 0; e < EMBED; e++) acc = fmaf(xs[b][e], ws[j][e], acc);
        g_XG[(t * G4 + j) * BATCH + b] = acc;
    }
}

// ---------------- K23: producer (block 0) + sumexp consumers ---------------
__global__ __launch_bounds__(256, 2) void k23_fused(
    const float* __restrict__ Whh, const float* __restrict__ h0,
    const float* __restrict__ c0,  const float* __restrict__ Wout,
    const float* __restrict__ bout) {
    const int tid = threadIdx.x;

    if (blockIdx.x == 0) {
        // ============ producer: LSTM recurrence ============
        const int u = tid >> 4, l = tid & 15;
        const int b0 = l, b1 = l + 16;
        __shared__ float hs[2][HID][BATCH];
        __shared__ unsigned long long wp[4][HID][8];

        for (int i = tid; i < 4 * HID * 8; i += 256) {
            int g = i >> 7, rest = i & 127, uu = rest >> 3, p = rest & 7;
            const float* row = Whh + (g * HID + uu) * HID;
            wp[g][uu][p] = pk2(row[2 * p], row[2 * p + 1]);
        }
        for (int i = tid; i < HID * BATCH; i += 256) {
            int uu = i >> 5, b = i & 31;
            hs[0][uu][b] = h0[b * HID + uu];
        }
        float cc0 = c0[b0 * HID + u], cc1 = c0[b1 * HID + u];

        float xgn0[4], xgn1[4];
#pragma unroll
        for (int g = 0; g < 4; g++) {
            xgn0[g] = g_XG[(g * HID + u) * BATCH + b0];
            xgn1[g] = g_XG[(g * HID + u) * BATCH + b1];
        }
        __syncthreads();

        int cur = 0;
        for (int t = 0; t < SEQ; t++) {
            float xg0[4], xg1[4];
#pragma unroll
            for (int g = 0; g < 4; g++) { xg0[g] = xgn0[g]; xg1[g] = xgn1[g]; }
            if (t + 1 < SEQ) {
                const float* base = g_XG + (t + 1) * G4 * BATCH;
#pragma unroll
                for (int g = 0; g < 4; g++) {
                    xgn0[g] = base[(g * HID + u) * BATCH + b0];
                    xgn1[g] = base[(g * HID + u) * BATCH + b1];
                }
            }
            unsigned long long h2a[8], h2b[8];
#pragma unroll
            for (int p = 0; p < 8; p++) {
                h2a[p] = pk2(hs[cur][2 * p][b0], hs[cur][2 * p + 1][b0]);
                h2b[p] = pk2(hs[cur][2 * p][b1], hs[cur][2 * p + 1][b1]);
            }
            float ga[4], gb[4];
#pragma unroll
            for (int g = 0; g < 4; g++) {
                unsigned long long a0 = 0ull, a1 = 0ull;
#pragma unroll
                for (int p = 0; p < 8; p++) {
                    unsigned long long w = wp[g][u][p];
                    a0 = fma2(w, h2a[p], a0);
                    a1 = fma2(w, h2b[p], a1);
                }
                ga[g] = hsum2(a0) + xg0[g];
                gb[g] = hsum2(a1) + xg1[g];
            }
            float hn0, hn1;
            {
                float ii = sgm(ga[0]), ff = sgm(ga[1]);
                float gg = tanha(ga[2]), oo = sgm(ga[3]);
                cc0 = ff * cc0 + ii * gg;
                hn0 = oo * tanha(cc0);
            }
            {
                float ii = sgm(gb[0]), ff = sgm(gb[1]);
                float gg = tanha(gb[2]), oo = sgm(gb[3]);
                cc1 = ff * cc1 + ii * gg;
                hn1 = oo * tanha(cc1);
            }
            hs[cur ^ 1][u][b0] = hn0;
            hs[cur ^ 1][u][b1] = hn1;
            float* gh = g_H + t * (HID * BATCH);
            gh[u * BATCH + b0] = hn0;
            gh[u * BATCH + b1] = hn1;
            __syncthreads();
            if (tid == 0) { __threadfence(); atomicExch(&g_flagH[t], 1u); }
            cur ^= 1;
        }
        return;
    }

    // ============ consumers: sum(exp(logits)), 4 vocab/thread ============
    const int bid   = blockIdx.x - 1;
    const int t     = bid >> 5;            // /NCHUNK, ascending with bid
    const int chunk = bid & (NCHUNK - 1);
    const int v0    = chunk * 1024 + 4 * tid;
    const bool ok   = v0 < VOCAB;          // v0 mult of 4, VOCAB mult of 4

    unsigned long long w[4][8];
    float bb[4];
    load_w4(Wout, bout, v0, ok, w, bb);

    __shared__ __align__(16) unsigned long long h2s[BATCH][8];
    __shared__ float bsum[BATCH];

    if (tid == 0) {
        while (ld_acq(&g_flagH[t]) == 0u) __nanosleep(32);
    }
    __syncthreads();
    {
        int b = tid >> 3, p = tid & 7;
        const float* gh = g_H + t * (HID * BATCH);
        h2s[b][p] = pk2(__ldcg(gh + (2 * p) * BATCH + b),
                        __ldcg(gh + (2 * p + 1) * BATCH + b));
    }
    if (tid < BATCH) bsum[tid] = 0.f;
    __syncthreads();

    const int lane = tid & 31;
#pragma unroll 4
    for (int b = 0; b < BATCH; b++) {
        unsigned long long a0 = pk2(bb[0], 0.f);
        unsigned long long a1 = pk2(bb[1], 0.f);
        unsigned long long a2 = pk2(bb[2], 0.f);
        unsigned long long a3 = pk2(bb[3], 0.f);
#pragma unroll
        for (int p = 0; p < 8; p++) {
            unsigned long long h = h2s[b][p];
            a0 = fma2(w[0][p], h, a0);
            a1 = fma2(w[1][p], h, a1);
            a2 = fma2(w[2][p], h, a2);
            a3 = fma2(w[3][p], h, a3);
        }
        float e = 0.f;
        if (ok) {
            e = __expf(hsum2(a0)) + __expf(hsum2(a1)) +
                __expf(hsum2(a2)) + __expf(hsum2(a3));
        }
#pragma unroll
        for (int m = 16; m > 0; m >>= 1)
            e += __shfl_xor_sync(0xffffffffu, e, m);
        if (lane == 0) atomicAdd(&bsum[b], e);
    }
    __syncthreads();
    if (tid < BATCH) atomicAdd(&g_rowsum[t * BATCH + tid], bsum[tid]);
}

// ---------------- K4: write logprobs (no dependencies, no spins) -----------
__global__ __launch_bounds__(256, 2) void k4_write(
    const float* __restrict__ Wout, const float* __restrict__ bout,
    float* __restrict__ out) {
    const int t = blockIdx.y, tid = threadIdx.x;
    const int chunk = blockIdx.x;
    const int v0 = chunk * 1024 + 4 * tid;
    const bool ok = v0 < VOCAB;

    unsigned long long w[4][8];
    float bb[4];
    load_w4(Wout, bout, v0, ok, w, bb);

    __shared__ __align__(16) unsigned long long h2s[BATCH][8];
    __shared__ float lseS[BATCH];
    if (tid < BATCH) lseS[tid] = __logf(g_rowsum[t * BATCH + tid]);
    {
        int b = tid >> 3, p = tid & 7;
        const float* gh = g_H + t * (HID * BATCH);
        h2s[b][p] = pk2(gh[(2 * p) * BATCH + b], gh[(2 * p + 1) * BATCH + b]);
    }
    __syncthreads();

    if (!ok) return;
    float* orow = out + ((size_t)t * BATCH) * VOCAB + v0;
#pragma unroll 4
    for (int b = 0; b < BATCH; b++) {
        unsigned long long a0 = pk2(bb[0], 0.f);
        unsigned long long a1 = pk2(bb[1], 0.f);
        unsigned long long a2 = pk2(bb[2], 0.f);
        unsigned long long a3 = pk2(bb[3], 0.f);
#pragma unroll
        for (int p = 0; p < 8; p++) {
            unsigned long long h = h2s[b][p];
            a0 = fma2(w[0][p], h, a0);
            a1 = fma2(w[1][p], h, a1);
            a2 = fma2(w[2][p], h, a2);
            a3 = fma2(w[3][p], h, a3);
        }
        float L = lseS[b];
        float4 o;
        o.x = hsum2(a0) - L;
        o.y = hsum2(a1) - L;
        o.z = hsum2(a2) - L;
        o.w = hsum2(a3) - L;
        *(float4*)(orow + (size_t)b * VOCAB) = o;
    }
}

// ---------------- launch ----------------
extern "C" void kernel_launch(void* const* d_in, const int* in_sizes, int n_in,
                              void* d_out, int out_size) {
    const int*   idx  = (const int*)  d_in[0];
    const float* emb  = (const float*)d_in[1];
    const float* Wih  = (const float*)d_in[2];
    const float* Whh  = (const float*)d_in[3];
    const float* bih  = (const float*)d_in[4];
    const float* bhh  = (const float*)d_in[5];
    const float* Wout = (const float*)d_in[6];
    const float* bout = (const float*)d_in[7];
    const float* h0   = (const float*)d_in[8];
    const float* c0   = (const float*)d_in[9];
    float* out = (float*)d_out;

    k1_xgates<<<SEQ, 256>>>(idx, emb, Wih, bih, bhh);
    k23_fused<<<1 + SEQ * NCHUNK, 256>>>(Whh, h0, c0, Wout, bout);
    k4_write<<<dim3(NCHUNK, SEQ), 256>>>(Wout, bout, out);
}

// round 8
// speedup vs baseline: 1.4449x; 1.0880x over previous
#include <cuda_runtime.h>
#include <cuda_bf16.h>

#define VOCAB 32000
#define EMBED 32
#define HID   16
#define SEQ   128
#define BATCH 32
#define G4    64
#define NCHUNK 32      // 1024-vocab chunks per timestep

// ---------------- scratch (device globals; no allocation) ----------------
__device__ float g_XG[SEQ * G4 * BATCH];   // [t][gate*HID+u][b]
__device__ float g_H [SEQ * HID * BATCH];  // [t][k][b]
__device__ float g_rowsum[SEQ * BATCH];
__device__ unsigned g_flagH[SEQ];

// ---------------- helpers ----------------
__device__ __forceinline__ unsigned long long pk2(float lo, float hi) {
    unsigned long long r;
    asm("mov.b64 %0, {%1, %2};" : "=l"(r) : "f"(lo), "f"(hi));
    return r;
}
__device__ __forceinline__ unsigned long long fma2(unsigned long long a,
                                                   unsigned long long b,
                                                   unsigned long long c) {
    unsigned long long d;
    asm("fma.rn.f32x2 %0, %1, %2, %3;" : "=l"(d) : "l"(a), "l"(b), "l"(c));
    return d;
}
__device__ __forceinline__ float hsum2(unsigned long long v) {
    float lo, hi;
    asm("mov.b64 {%0, %1}, %2;" : "=f"(lo), "=f"(hi) : "l"(v));
    return lo + hi;
}
__device__ __forceinline__ float tanha(float x) {
    float y;
    asm("tanh.approx.f32 %0, %1;" : "=f"(y) : "f"(x));
    return y;
}
__device__ __forceinline__ float sgm(float x) {
    return fmaf(tanha(0.5f * x), 0.5f, 0.5f);
}
__device__ __forceinline__ unsigned ld_acq(const unsigned* p) {
    unsigned v;
    asm volatile("ld.acquire.gpu.u32 %0, [%1];" : "=r"(v) : "l"(p) : "memory");
    return v;
}
__device__ __forceinline__ void stcs4(float* p, float4 v) {
    asm volatile("st.global.cs.v4.f32 [%0], {%1, %2, %3, %4};"
                 :: "l"(p), "f"(v.x), "f"(v.y), "f"(v.z), "f"(v.w) : "memory");
}

// load 4 weight rows (v0..v0+3) packed as f32x2, plus biases
__device__ __forceinline__ void load_w4(const float* __restrict__ Wout,
                                        const float* __restrict__ bout,
                                        int v0, bool ok,
                                        unsigned long long w[4][8], float bb[4]) {
    if (ok) {
        const float4* wv = (const float4*)(Wout + (size_t)v0 * HID);
#pragma unroll
        for (int r = 0; r < 4; r++) {
#pragma unroll
            for (int q = 0; q < 4; q++) {
                float4 f = wv[r * 4 + q];
                w[r][2 * q] = pk2(f.x, f.y);
                w[r][2 * q + 1] = pk2(f.z, f.w);
            }
            bb[r] = bout[v0 + r];
        }
    } else {
#pragma unroll
        for (int r = 0; r < 4; r++) {
#pragma unroll
            for (int p = 0; p < 8; p++) w[r][p] = 0ull;
            bb[r] = 0.f;
        }
    }
}

// compute sum of 4 exps of logits for batch b (weights in w, h in h2s[b])
__device__ __forceinline__ float expsum4(const unsigned long long w[4][8],
                                         const float bb[4],
                                         const unsigned long long* h2b) {
    unsigned long long a0 = pk2(bb[0], 0.f);
    unsigned long long a1 = pk2(bb[1], 0.f);
    unsigned long long a2 = pk2(bb[2], 0.f);
    unsigned long long a3 = pk2(bb[3], 0.f);
#pragma unroll
    for (int p = 0; p < 8; p++) {
        unsigned long long h = h2b[p];
        a0 = fma2(w[0][p], h, a0);
        a1 = fma2(w[1][p], h, a1);
        a2 = fma2(w[2][p], h, a2);
        a3 = fma2(w[3][p], h, a3);
    }
    return __expf(hsum2(a0)) + __expf(hsum2(a1)) +
           __expf(hsum2(a2)) + __expf(hsum2(a3));
}

// ---------------- K1: input-side gate preacts + scratch reset --------------
__global__ __launch_bounds__(256) void k1_xgates(
    const int* __restrict__ idx, const float* __restrict__ emb,
    const float* __restrict__ Wih, const float* __restrict__ bih,
    const float* __restrict__ bhh) {
    __shared__ float xs[BATCH][EMBED + 1];
    __shared__ float ws[G4][EMBED];
    __shared__ float bias[G4];
    const int t = blockIdx.x, tid = threadIdx.x;

    if (tid == 0) g_flagH[t] = 0u;
    if (tid < BATCH) g_rowsum[t * BATCH + tid] = 0.f;

    for (int i = tid; i < BATCH * EMBED; i += 256) {
        int b = i >> 5, e = i & 31;
        xs[b][e] = emb[idx[t * BATCH + b] * EMBED + e];
    }
    for (int i = tid; i < G4 * EMBED; i += 256) ws[i >> 5][i & 31] = Wih[i];
    if (tid < G4) bias[tid] = bih[tid] + bhh[tid];
    __syncthreads();

    for (int i = tid; i < G4 * BATCH; i += 256) {
        int j = i >> 5, b = i & 31;
        float acc = bias[j];
#pragma unroll
        for (int e = 0; e < EMBED; e++) acc = fmaf(xs[b][e], ws[j][e], acc);
        g_XG[(t * G4 + j) * BATCH + b] = acc;
    }
}

// ---------------- K23: producer (block 0) + sumexp consumers ---------------
__global__ __launch_bounds__(256, 2) void k23_fused(
    const float* __restrict__ Whh, const float* __restrict__ h0,
    const float* __restrict__ c0,  const float* __restrict__ Wout,
    const float* __restrict__ bout) {
    const int tid = threadIdx.x;

    if (blockIdx.x == 0) {
        // ============ producer: LSTM recurrence ============
        const int u = tid >> 4, l = tid & 15;
        const int b0 = l, b1 = l + 16;
        __shared__ float hs[2][HID][BATCH];
        __shared__ unsigned long long wp[4][HID][8];

        for (int i = tid; i < 4 * HID * 8; i += 256) {
            int g = i >> 7, rest = i & 127, uu = rest >> 3, p = rest & 7;
            const float* row = Whh + (g * HID + uu) * HID;
            wp[g][uu][p] = pk2(row[2 * p], row[2 * p + 1]);
        }
        for (int i = tid; i < HID * BATCH; i += 256) {
            int uu = i >> 5, b = i & 31;
            hs[0][uu][b] = h0[b * HID + uu];
        }
        float cc0 = c0[b0 * HID + u], cc1 = c0[b1 * HID + u];

        float xgn0[4], xgn1[4];
#pragma unroll
        for (int g = 0; g < 4; g++) {
            xgn0[g] = g_XG[(g * HID + u) * BATCH + b0];
            xgn1[g] = g_XG[(g * HID + u) * BATCH + b1];
        }
        __syncthreads();

        int cur = 0;
        for (int t = 0; t < SEQ; t++) {
            float xg0[4], xg1[4];
#pragma unroll
            for (int g = 0; g < 4; g++) { xg0[g] = xgn0[g]; xg1[g] = xgn1[g]; }
            if (t + 1 < SEQ) {
                const float* base = g_XG + (t + 1) * G4 * BATCH;
#pragma unroll
                for (int g = 0; g < 4; g++) {
                    xgn0[g] = base[(g * HID + u) * BATCH + b0];
                    xgn1[g] = base[(g * HID + u) * BATCH + b1];
                }
            }
            unsigned long long h2a[8], h2b[8];
#pragma unroll
            for (int p = 0; p < 8; p++) {
                h2a[p] = pk2(hs[cur][2 * p][b0], hs[cur][2 * p + 1][b0]);
                h2b[p] = pk2(hs[cur][2 * p][b1], hs[cur][2 * p + 1][b1]);
            }
            float ga[4], gb[4];
#pragma unroll
            for (int g = 0; g < 4; g++) {
                unsigned long long a0 = 0ull, a1 = 0ull;
#pragma unroll
                for (int p = 0; p < 8; p++) {
                    unsigned long long w = wp[g][u][p];
                    a0 = fma2(w, h2a[p], a0);
                    a1 = fma2(w, h2b[p], a1);
                }
                ga[g] = hsum2(a0) + xg0[g];
                gb[g] = hsum2(a1) + xg1[g];
            }
            float hn0, hn1;
            {
                float ii = sgm(ga[0]), ff = sgm(ga[1]);
                float gg = tanha(ga[2]), oo = sgm(ga[3]);
                cc0 = ff * cc0 + ii * gg;
                hn0 = oo * tanha(cc0);
            }
            {
                float ii = sgm(gb[0]), ff = sgm(gb[1]);
                float gg = tanha(gb[2]), oo = sgm(gb[3]);
                cc1 = ff * cc1 + ii * gg;
                hn1 = oo * tanha(cc1);
            }
            hs[cur ^ 1][u][b0] = hn0;
            hs[cur ^ 1][u][b1] = hn1;
            float* gh = g_H + t * (HID * BATCH);
            gh[u * BATCH + b0] = hn0;
            gh[u * BATCH + b1] = hn1;
            __syncthreads();
            if (tid == 0) { __threadfence(); atomicExch(&g_flagH[t], 1u); }
            cur ^= 1;
        }
        return;
    }

    // ===== consumers: sum(exp(logits)), 4 vocab/thread, 4-batch groups =====
    const int bid   = blockIdx.x - 1;
    const int t     = bid >> 5;
    const int chunk = bid & (NCHUNK - 1);
    const int v0    = chunk * 1024 + 4 * tid;
    const bool ok   = v0 < VOCAB;

    unsigned long long w[4][8];
    float bb[4];
    load_w4(Wout, bout, v0, ok, w, bb);

    __shared__ __align__(16) unsigned long long h2s[BATCH][8];
    __shared__ float bsum[BATCH];

    if (tid == 0) {
        while (ld_acq(&g_flagH[t]) == 0u) __nanosleep(32);
    }
    __syncthreads();
    {
        int b = tid >> 3, p = tid & 7;
        const float* gh = g_H + t * (HID * BATCH);
        h2s[b][p] = pk2(__ldcg(gh + (2 * p) * BATCH + b),
                        __ldcg(gh + (2 * p + 1) * BATCH + b));
    }
    if (tid < BATCH) bsum[tid] = 0.f;
    __syncthreads();

    const int lane = tid & 31;
#pragma unroll
    for (int b4 = 0; b4 < BATCH; b4 += 4) {
        float e0 = 0.f, e1 = 0.f, e2 = 0.f, e3 = 0.f;
        if (ok) {
            e0 = expsum4(w, bb, h2s[b4 + 0]);
            e1 = expsum4(w, bb, h2s[b4 + 1]);
            e2 = expsum4(w, bb, h2s[b4 + 2]);
            e3 = expsum4(w, bb, h2s[b4 + 3]);
        }
        // 4 independent butterfly chains — latency overlapped
#pragma unroll
        for (int m = 16; m > 0; m >>= 1) {
            e0 += __shfl_xor_sync(0xffffffffu, e0, m);
            e1 += __shfl_xor_sync(0xffffffffu, e1, m);
            e2 += __shfl_xor_sync(0xffffffffu, e2, m);
            e3 += __shfl_xor_sync(0xffffffffu, e3, m);
        }
        if (lane == 0) {
            atomicAdd(&bsum[b4 + 0], e0);
            atomicAdd(&bsum[b4 + 1], e1);
            atomicAdd(&bsum[b4 + 2], e2);
            atomicAdd(&bsum[b4 + 3], e3);
        }
    }
    __syncthreads();
    if (tid < BATCH) atomicAdd(&g_rowsum[t * BATCH + tid], bsum[tid]);
}

// ---------------- K4: write logprobs (no dependencies, no spins) -----------
__global__ __launch_bounds__(256, 2) void k4_write(
    const float* __restrict__ Wout, const float* __restrict__ bout,
    float* __restrict__ out) {
    const int t = blockIdx.y, tid = threadIdx.x;
    const int chunk = blockIdx.x;
    const int v0 = chunk * 1024 + 4 * tid;
    const bool ok = v0 < VOCAB;

    unsigned long long w[4][8];
    float bb[4];
    load_w4(Wout, bout, v0, ok, w, bb);

    __shared__ __align__(16) unsigned long long h2s[BATCH][8];
    __shared__ float lseS[BATCH];
    if (tid < BATCH) lseS[tid] = __logf(g_rowsum[t * BATCH + tid]);
    {
        int b = tid >> 3, p = tid & 7;
        const float* gh = g_H + t * (HID * BATCH);
        h2s[b][p] = pk2(gh[(2 * p) * BATCH + b], gh[(2 * p + 1) * BATCH + b]);
    }
    __syncthreads();

    if (!ok) return;
    float* orow = out + ((size_t)t * BATCH) * VOCAB + v0;
#pragma unroll 4
    for (int b = 0; b < BATCH; b++) {
        unsigned long long a0 = pk2(bb[0], 0.f);
        unsigned long long a1 = pk2(bb[1], 0.f);
        unsigned long long a2 = pk2(bb[2], 0.f);
        unsigned long long a3 = pk2(bb[3], 0.f);
#pragma unroll
        for (int p = 0; p < 8; p++) {
            unsigned long long h = h2s[b][p];
            a0 = fma2(w[0][p], h, a0);
            a1 = fma2(w[1][p], h, a1);
            a2 = fma2(w[2][p], h, a2);
            a3 = fma2(w[3][p], h, a3);
        }
        float L = lseS[b];
        float4 o;
        o.x = hsum2(a0) - L;
        o.y = hsum2(a1) - L;
        o.z = hsum2(a2) - L;
        o.w = hsum2(a3) - L;
        stcs4(orow + (size_t)b * VOCAB, o);
    }
}

// ---------------- launch ----------------
extern "C" void kernel_launch(void* const* d_in, const int* in_sizes, int n_in,
                              void* d_out, int out_size) {
    const int*   idx  = (const int*)  d_in[0];
    const float* emb  = (const float*)d_in[1];
    const float* Wih  = (const float*)d_in[2];
    const float* Whh  = (const float*)d_in[3];
    const float* bih  = (const float*)d_in[4];
    const float* bhh  = (const float*)d_in[5];
    const float* Wout = (const float*)d_in[6];
    const float* bout = (const float*)d_in[7];
    const float* h0   = (const float*)d_in[8];
    const float* c0   = (const float*)d_in[9];
    float* out = (float*)d_out;

    k1_xgates<<<SEQ, 256>>>(idx, emb, Wih, bih, bhh);
    k23_fused<<<1 + SEQ * NCHUNK, 256>>>(Whh, h0, c0, Wout, bout);
    k4_write<<<dim3(NCHUNK, SEQ), 256>>>(Wout, bout, out);
}

// round 9
// speedup vs baseline: 1.5289x; 1.0581x over previous
#include <cuda_runtime.h>
#include <cuda_bf16.h>

#define VOCAB 32000
#define EMBED 32
#define HID   16
#define SEQ   128
#define BATCH 32
#define G4    64
#define NCHUNK 32      // 1024-vocab chunks per timestep

// ---------------- scratch (device globals; no allocation) ----------------
__device__ float g_XG[SEQ * G4 * BATCH];   // [t][gate*HID+u][b]
__device__ float g_H [SEQ * HID * BATCH];  // [t][k][b]
__device__ float g_rowsum[SEQ * BATCH];
__device__ unsigned g_flagH[SEQ];
__device__ unsigned g_cnt[SEQ];

// ---------------- helpers ----------------
__device__ __forceinline__ unsigned long long pk2(float lo, float hi) {
    unsigned long long r;
    asm("mov.b64 %0, {%1, %2};" : "=l"(r) : "f"(lo), "f"(hi));
    return r;
}
__device__ __forceinline__ unsigned long long fma2(unsigned long long a,
                                                   unsigned long long b,
                                                   unsigned long long c) {
    unsigned long long d;
    asm("fma.rn.f32x2 %0, %1, %2, %3;" : "=l"(d) : "l"(a), "l"(b), "l"(c));
    return d;
}
__device__ __forceinline__ float hsum2(unsigned long long v) {
    float lo, hi;
    asm("mov.b64 {%0, %1}, %2;" : "=f"(lo), "=f"(hi) : "l"(v));
    return lo + hi;
}
__device__ __forceinline__ float tanha(float x) {
    float y;
    asm("tanh.approx.f32 %0, %1;" : "=f"(y) : "f"(x));
    return y;
}
__device__ __forceinline__ float sgm(float x) {
    return fmaf(tanha(0.5f * x), 0.5f, 0.5f);
}
__device__ __forceinline__ unsigned ld_acq(const unsigned* p) {
    unsigned v;
    asm volatile("ld.acquire.gpu.u32 %0, [%1];" : "=r"(v) : "l"(p) : "memory");
    return v;
}
__device__ __forceinline__ float ld_acq_f(const float* p) {
    float v;
    asm volatile("ld.acquire.gpu.f32 %0, [%1];" : "=f"(v) : "l"(p) : "memory");
    return v;
}
__device__ __forceinline__ void stcs4(float* p, float4 v) {
    asm volatile("st.global.cs.v4.f32 [%0], {%1, %2, %3, %4};"
                 :: "l"(p), "f"(v.x), "f"(v.y), "f"(v.z), "f"(v.w) : "memory");
}

// compute sum of 4 exps of logits for one batch column
__device__ __forceinline__ float expsum4(const unsigned long long w[4][8],
                                         const float bb[4],
                                         const unsigned long long* h2b) {
    unsigned long long a0 = pk2(bb[0], 0.f);
    unsigned long long a1 = pk2(bb[1], 0.f);
    unsigned long long a2 = pk2(bb[2], 0.f);
    unsigned long long a3 = pk2(bb[3], 0.f);
#pragma unroll
    for (int p = 0; p < 8; p++) {
        unsigned long long h = h2b[p];
        a0 = fma2(w[0][p], h, a0);
        a1 = fma2(w[1][p], h, a1);
        a2 = fma2(w[2][p], h, a2);
        a3 = fma2(w[3][p], h, a3);
    }
    return __expf(hsum2(a0)) + __expf(hsum2(a1)) +
           __expf(hsum2(a2)) + __expf(hsum2(a3));
}

// ---------------- K1: input-side gate preacts + scratch reset --------------
__global__ __launch_bounds__(256) void k1_xgates(
    const int* __restrict__ idx, const float* __restrict__ emb,
    const float* __restrict__ Wih, const float* __restrict__ bih,
    const float* __restrict__ bhh) {
    __shared__ float xs[BATCH][EMBED + 1];
    __shared__ float ws[G4][EMBED];
    __shared__ float bias[G4];
    const int t = blockIdx.x, tid = threadIdx.x;

    if (tid == 0) { g_flagH[t] = 0u; g_cnt[t] = 0u; }
    if (tid < BATCH) g_rowsum[t * BATCH + tid] = 0.f;

    for (int i = tid; i < BATCH * EMBED; i += 256) {
        int b = i >> 5, e = i & 31;
        xs[b][e] = emb[idx[t * BATCH + b] * EMBED + e];
    }
    for (int i = tid; i < G4 * EMBED; i += 256) ws[i >> 5][i & 31] = Wih[i];
    if (tid < G4) bias[tid] = bih[tid] + bhh[tid];
    __syncthreads();

    for (int i = tid; i < G4 * BATCH; i += 256) {
        int j = i >> 5, b = i & 31;
        float acc = bias[j];
#pragma unroll
        for (int e = 0; e < EMBED; e++) acc = fmaf(xs[b][e], ws[j][e], acc);
        g_XG[(t * G4 + j) * BATCH + b] = acc;
    }
}

// ---- fused: producer (block 0) + consumers doing K3 then K4 in-place ------
__global__ __launch_bounds__(256, 2) void k_fused(
    const float* __restrict__ Whh, const float* __restrict__ h0,
    const float* __restrict__ c0,  const float* __restrict__ Wout,
    const float* __restrict__ bout, float* __restrict__ out) {
    const int tid = threadIdx.x;

    if (blockIdx.x == 0) {
        // ============ producer: LSTM recurrence ============
        const int u = tid >> 4, l = tid & 15;
        const int b0 = l, b1 = l + 16;
        __shared__ float hs[2][HID][BATCH];
        __shared__ unsigned long long wp[4][HID][8];

        for (int i = tid; i < 4 * HID * 8; i += 256) {
            int g = i >> 7, rest = i & 127, uu = rest >> 3, p = rest & 7;
            const float* row = Whh + (g * HID + uu) * HID;
            wp[g][uu][p] = pk2(row[2 * p], row[2 * p + 1]);
        }
        for (int i = tid; i < HID * BATCH; i += 256) {
            int uu = i >> 5, b = i & 31;
            hs[0][uu][b] = h0[b * HID + uu];
        }
        float cc0 = c0[b0 * HID + u], cc1 = c0[b1 * HID + u];

        float xgn0[4], xgn1[4];
#pragma unroll
        for (int g = 0; g < 4; g++) {
            xgn0[g] = g_XG[(g * HID + u) * BATCH + b0];
            xgn1[g] = g_XG[(g * HID + u) * BATCH + b1];
        }
        __syncthreads();

        int cur = 0;
        for (int t = 0; t < SEQ; t++) {
            float xg0[4], xg1[4];
#pragma unroll
            for (int g = 0; g < 4; g++) { xg0[g] = xgn0[g]; xg1[g] = xgn1[g]; }
            if (t + 1 < SEQ) {
                const float* base = g_XG + (t + 1) * G4 * BATCH;
#pragma unroll
                for (int g = 0; g < 4; g++) {
                    xgn0[g] = base[(g * HID + u) * BATCH + b0];
                    xgn1[g] = base[(g * HID + u) * BATCH + b1];
                }
            }
            unsigned long long h2a[8], h2b[8];
#pragma unroll
            for (int p = 0; p < 8; p++) {
                h2a[p] = pk2(hs[cur][2 * p][b0], hs[cur][2 * p + 1][b0]);
                h2b[p] = pk2(hs[cur][2 * p][b1], hs[cur][2 * p + 1][b1]);
            }
            float ga[4], gb[4];
#pragma unroll
            for (int g = 0; g < 4; g++) {
                unsigned long long a0 = 0ull, a1 = 0ull;
#pragma unroll
                for (int p = 0; p < 8; p++) {
                    unsigned long long w = wp[g][u][p];
                    a0 = fma2(w, h2a[p], a0);
                    a1 = fma2(w, h2b[p], a1);
                }
                ga[g] = hsum2(a0) + xg0[g];
                gb[g] = hsum2(a1) + xg1[g];
            }
            float hn0, hn1;
            {
                float ii = sgm(ga[0]), ff = sgm(ga[1]);
                float gg = tanha(ga[2]), oo = sgm(ga[3]);
                cc0 = ff * cc0 + ii * gg;
                hn0 = oo * tanha(cc0);
            }
            {
                float ii = sgm(gb[0]), ff = sgm(gb[1]);
                float gg = tanha(gb[2]), oo = sgm(gb[3]);
                cc1 = ff * cc1 + ii * gg;
                hn1 = oo * tanha(cc1);
            }
            hs[cur ^ 1][u][b0] = hn0;
            hs[cur ^ 1][u][b1] = hn1;
            float* gh = g_H + t * (HID * BATCH);
            gh[u * BATCH + b0] = hn0;
            gh[u * BATCH + b1] = hn1;
            __syncthreads();
            if (tid == 0) { __threadfence(); atomicExch(&g_flagH[t], 1u); }
            cur ^= 1;
        }
        return;
    }

    // ================= consumers: K3 then K4, weights resident =============
    const int bid   = blockIdx.x - 1;
    const int t     = bid >> 5;            // ascending with block index
    const int chunk = bid & (NCHUNK - 1);
    const int v0    = chunk * 1024 + 4 * tid;
    const bool ok   = v0 < VOCAB;

    // weight rows v0..v0+3, resident for BOTH phases
    unsigned long long w[4][8];
    float bb[4];
    if (ok) {
        const float4* wv = (const float4*)(Wout + (size_t)v0 * HID);
#pragma unroll
        for (int r = 0; r < 4; r++) {
#pragma unroll
            for (int q = 0; q < 4; q++) {
                float4 f = wv[r * 4 + q];
                w[r][2 * q] = pk2(f.x, f.y);
                w[r][2 * q + 1] = pk2(f.z, f.w);
            }
            bb[r] = bout[v0 + r];
        }
    } else {
#pragma unroll
        for (int r = 0; r < 4; r++) {
#pragma unroll
            for (int p = 0; p < 8; p++) w[r][p] = 0ull;
            bb[r] = 0.f;
        }
    }

    __shared__ __align__(16) unsigned long long h2s[BATCH][8];
    __shared__ float bsum[BATCH];
    __shared__ float lseS[BATCH];

    // ---- wait for h(t) (producer only; always ahead) ----
    if (tid == 0) {
        while (ld_acq(&g_flagH[t]) == 0u) __nanosleep(32);
    }
    __syncthreads();
    {
        int b = tid >> 3, p = tid & 7;
        const float* gh = g_H + t * (HID * BATCH);
        h2s[b][p] = pk2(__ldcg(gh + (2 * p) * BATCH + b),
                        __ldcg(gh + (2 * p + 1) * BATCH + b));
    }
    if (tid < BATCH) bsum[tid] = 0.f;
    __syncthreads();

    // ---- K3 phase: sum of exps ----
    const int lane = tid & 31;
#pragma unroll
    for (int b4 = 0; b4 < BATCH; b4 += 4) {
        float e0 = 0.f, e1 = 0.f, e2 = 0.f, e3 = 0.f;
        if (ok) {
            e0 = expsum4(w, bb, h2s[b4 + 0]);
            e1 = expsum4(w, bb, h2s[b4 + 1]);
            e2 = expsum4(w, bb, h2s[b4 + 2]);
            e3 = expsum4(w, bb, h2s[b4 + 3]);
        }
#pragma unroll
        for (int m = 16; m > 0; m >>= 1) {
            e0 += __shfl_xor_sync(0xffffffffu, e0, m);
            e1 += __shfl_xor_sync(0xffffffffu, e1, m);
            e2 += __shfl_xor_sync(0xffffffffu, e2, m);
            e3 += __shfl_xor_sync(0xffffffffu, e3, m);
        }
        if (lane == 0) {
            atomicAdd(&bsum[b4 + 0], e0);
            atomicAdd(&bsum[b4 + 1], e1);
            atomicAdd(&bsum[b4 + 2], e2);
            atomicAdd(&bsum[b4 + 3], e3);
        }
    }
    __syncthreads();
    if (tid < BATCH) {
        atomicAdd(&g_rowsum[t * BATCH + tid], bsum[tid]);
        __threadfence();
    }
    __syncthreads();

    // ---- rendezvous: all 32 chunks of this t done with K3 ----
    if (tid == 0) {
        atomicAdd(&g_cnt[t], 1u);
        while (ld_acq(&g_cnt[t]) < (unsigned)NCHUNK) __nanosleep(32);
    }
    __syncthreads();
    if (tid < BATCH) lseS[tid] = __logf(ld_acq_f(&g_rowsum[t * BATCH + tid]));
    __syncthreads();

    // ---- K4 phase: recompute logits (weights still in regs), store --------
    if (!ok) return;
    float* orow = out + ((size_t)t * BATCH) * VOCAB + v0;
#pragma unroll 4
    for (int b = 0; b < BATCH; b++) {
        unsigned long long a0 = pk2(bb[0], 0.f);
        unsigned long long a1 = pk2(bb[1], 0.f);
        unsigned long long a2 = pk2(bb[2], 0.f);
        unsigned long long a3 = pk2(bb[3], 0.f);
#pragma unroll
        for (int p = 0; p < 8; p++) {
            unsigned long long h = h2s[b][p];
            a0 = fma2(w[0][p], h, a0);
            a1 = fma2(w[1][p], h, a1);
            a2 = fma2(w[2][p], h, a2);
            a3 = fma2(w[3][p], h, a3);
        }
        float L = lseS[b];
        float4 o;
        o.x = hsum2(a0) - L;
        o.y = hsum2(a1) - L;
        o.z = hsum2(a2) - L;
        o.w = hsum2(a3) - L;
        stcs4(orow + (size_t)b * VOCAB, o);
    }
}

// ---------------- launch ----------------
extern "C" void kernel_launch(void* const* d_in, const int* in_sizes, int n_in,
                              void* d_out, int out_size) {
    const int*   idx  = (const int*)  d_in[0];
    const float* emb  = (const float*)d_in[1];
    const float* Wih  = (const float*)d_in[2];
    const float* Whh  = (const float*)d_in[3];
    const float* bih  = (const float*)d_in[4];
    const float* bhh  = (const float*)d_in[5];
    const float* Wout = (const float*)d_in[6];
    const float* bout = (const float*)d_in[7];
    const float* h0   = (const float*)d_in[8];
    const float* c0   = (const float*)d_in[9];
    float* out = (float*)d_out;

    k1_xgates<<<SEQ, 256>>>(idx, emb, Wih, bih, bhh);
    k_fused<<<1 + SEQ * NCHUNK, 256>>>(Whh, h0, c0, Wout, bout, out);
}